// round 1
// baseline (speedup 1.0000x reference)
#include <cuda_runtime.h>

#define NCLS 19
#define FPX  16384      // 128*128 feature pixels
#define DCH  64
#define LBL  512
#define NT   256

__device__ float g_cnt[NCLS * FPX];
__device__ float g_loss[NCLS * DCH];
__device__ float g_n[NCLS];

__device__ __forceinline__ float ex2f(float x) {
    float y;
    asm("ex2.approx.ftz.f32 %0, %1;" : "=f"(y) : "f"(x));
    return y;
}

// K1: per-feature-pixel class counts over each 4x4 label block.
__global__ void count_kernel(const int* __restrict__ label) {
    int fp = blockIdx.x * blockDim.x + threadIdx.x;
    if (fp >= FPX) return;
    int r = fp >> 7, c = fp & 127;
    int labs[16];
#pragma unroll
    for (int dr = 0; dr < 4; dr++) {
        int4 v = *reinterpret_cast<const int4*>(label + (4 * r + dr) * LBL + 4 * c);
        labs[dr * 4 + 0] = v.x; labs[dr * 4 + 1] = v.y;
        labs[dr * 4 + 2] = v.z; labs[dr * 4 + 3] = v.w;
    }
#pragma unroll
    for (int cls = 0; cls < NCLS; cls++) {
        int cnt = 0;
#pragma unroll
        for (int i = 0; i < 16; i++) cnt += (labs[i] == cls) ? 1 : 0;
        g_cnt[cls * FPX + fp] = (float)cnt;
    }
}

// K2: one block per (class, channel). Moments + weighted 7-bin KDE + smooth-L1.
__global__ __launch_bounds__(NT) void klass_kernel(const float* __restrict__ feat) {
    const int cls = blockIdx.x;
    const int dd  = blockIdx.y;
    const float4* __restrict__ f4 = reinterpret_cast<const float4*>(feat + dd * FPX);
    const float4* __restrict__ w4 = reinterpret_cast<const float4*>(g_cnt + cls * FPX);
    const int tid  = threadIdx.x;
    const int lane = tid & 31, wid = tid >> 5;

    __shared__ float red[10][8];

    // ---- phase 1: n, sum(w*f), sum(w*f^2) ----
    float s0 = 0.f, s1 = 0.f, s2 = 0.f;
    for (int i = tid; i < FPX / 4; i += NT) {
        float4 fv = f4[i];
        float4 wv = w4[i];
        s0 += wv.x + wv.y + wv.z + wv.w;
        s1 += wv.x * fv.x + wv.y * fv.y + wv.z * fv.z + wv.w * fv.w;
        s2 += wv.x * fv.x * fv.x + wv.y * fv.y * fv.y
            + wv.z * fv.z * fv.z + wv.w * fv.w * fv.w;
    }
#pragma unroll
    for (int o = 16; o; o >>= 1) {
        s0 += __shfl_xor_sync(0xffffffffu, s0, o);
        s1 += __shfl_xor_sync(0xffffffffu, s1, o);
        s2 += __shfl_xor_sync(0xffffffffu, s2, o);
    }
    if (lane == 0) { red[0][wid] = s0; red[1][wid] = s1; red[2][wid] = s2; }
    __syncthreads();
    float n = 0.f, S1 = 0.f, S2 = 0.f;
#pragma unroll
    for (int j = 0; j < 8; j++) { n += red[0][j]; S1 += red[1][j]; S2 += red[2][j]; }

    float nsafe = fmaxf(n, 1.0f);
    float miu   = S1 / nsafe;
    float var   = fmaxf(S2 / nsafe - miu * miu, 0.0f) + 1e-10f;
    float inv5  = 5.0f * rsqrtf(var);        // 5/std

    // ---- phase 2: 7-bin weighted KDE ----
    // exp(-0.5*z^2), z = 5k - u, u = 5(f-miu)/std
    // arg_k = C2*(u - k5)^2 = q*(u - 2*k5) + C2*k5^2,  q = C2*u
    const float C2 = -0.72134752f;            // -0.5 * log2(e)
    float acc[7] = {0.f, 0.f, 0.f, 0.f, 0.f, 0.f, 0.f};

    for (int i = tid; i < FPX / 4; i += NT) {
        float4 fv = f4[i];
        float4 wv = w4[i];
        const float fs[4] = {fv.x, fv.y, fv.z, fv.w};
        const float ws[4] = {wv.x, wv.y, wv.z, wv.w};
#pragma unroll
        for (int e = 0; e < 4; e++) {
            float u = (fs[e] - miu) * inv5;
            float q = C2 * u;
#pragma unroll
            for (int k = 0; k < 7; k++) {
                const float k5 = (float)(5 * (k - 3));
                float t   = u - 2.0f * k5;
                float arg = fmaf(q, t, C2 * k5 * k5);
                acc[k] = fmaf(ws[e], ex2f(arg), acc[k]);
            }
        }
    }

#pragma unroll
    for (int k = 0; k < 7; k++) {
        float v = acc[k];
#pragma unroll
        for (int o = 16; o; o >>= 1) v += __shfl_xor_sync(0xffffffffu, v, o);
        if (lane == 0) red[3 + k][wid] = v;
    }
    __syncthreads();

    if (tid == 0) {
        float s[7], tot = 0.f;
#pragma unroll
        for (int k = 0; k < 7; k++) {
            float v = 0.f;
#pragma unroll
            for (int j = 0; j < 8; j++) v += red[3 + k][j];
            s[k] = v; tot += v;
        }
        float inv = 1.0f / fmaxf(tot, 1e-30f);
        // exp(-0.5*k^2) normalized (target; all class/var factors cancel)
        const float targ[7] = {0.00443305f, 0.05400558f, 0.24203623f, 0.39905027f,
                               0.24203623f, 0.05400558f, 0.00443305f};
        float L = 0.f;
#pragma unroll
        for (int k = 0; k < 7; k++) {
            float dif = fabsf(s[k] * inv - targ[k]);
            L += (dif < 1.0f) ? 0.5f * dif * dif : (dif - 0.5f);
        }
        float active = (n >= 1000.0f) ? 1.0f : 0.0f;
        g_loss[cls * DCH + dd] = active * L * (1.0f / (7.0f * (float)DCH));
        if (dd == 0) g_n[cls] = n;
    }
}

// K3: final deterministic reduction -> scalar loss
__global__ void final_kernel(float* __restrict__ out) {
    const int tid  = threadIdx.x;
    const int lane = tid & 31, wid = tid >> 5;
    __shared__ float red[8];
    float s = 0.f;
    for (int i = tid; i < NCLS * DCH; i += NT) s += g_loss[i];
#pragma unroll
    for (int o = 16; o; o >>= 1) s += __shfl_xor_sync(0xffffffffu, s, o);
    if (lane == 0) red[wid] = s;
    __syncthreads();
    if (tid == 0) {
        float num = 0.f;
#pragma unroll
        for (int j = 0; j < 8; j++) num += red[j];
        float den = 0.f;
        for (int c = 0; c < NCLS; c++) den += (g_n[c] >= 1000.0f) ? 1.0f : 0.0f;
        out[0] = num / den;
    }
}

extern "C" void kernel_launch(void* const* d_in, const int* in_sizes, int n_in,
                              void* d_out, int out_size) {
    const float* feature;
    const int*   label;
    if (in_sizes[0] == DCH * FPX) {
        feature = (const float*)d_in[0];
        label   = (const int*)d_in[1];
    } else {
        feature = (const float*)d_in[1];
        label   = (const int*)d_in[0];
    }
    count_kernel<<<FPX / NT, NT>>>(label);
    klass_kernel<<<dim3(NCLS, DCH), NT>>>(feature);
    final_kernel<<<1, NT>>>((float*)d_out);
}